// round 8
// baseline (speedup 1.0000x reference)
#include <cuda_runtime.h>
#include <cuda_fp16.h>
#include <cstdint>

// ---------------------------------------------------------------------------
// GAT_37709812858998: 2-layer GAT + FC/BN/FC/log_softmax
// R8: no xprep; gemm1 = fp32-A software pipeline (LDG/cvt/STS) + cp.async B,
//     fp16 gemms full cp.async; __launch_bounds__(256,2) for 2 CTAs/SM.
// ---------------------------------------------------------------------------

#define MAXN 100096
#define MAXE 1700160

__device__ float  g_A[(size_t)MAXN * 128];   // h_src as __half (aliased)
__device__ float  g_B[(size_t)MAXN * 128];   // layer out as __half (aliased)
__device__ float  g_h3[(size_t)MAXN * 64];
__device__ float  g_asrc[MAXN];
__device__ float  g_adst[MAXN];
__device__ float  g_wda[256];
__device__ __half g_Wt[128 * 256];           // transposed fp16 weights [ND][KD]
__device__ int    g_deg[MAXN];
__device__ int    g_off[MAXN];
__device__ int    g_cur[MAXN];
__device__ int    g_scan[MAXN];
__device__ int    g_bsum[256];
__device__ int    g_esrc[MAXE];
__device__ float  g_bn[128];
__device__ float  g_mu[64];
__device__ float  g_rstd[64];
__device__ int    g_is64;

#define SWZ(o) ((o) ^ (((o) >> 3) & 0x70))

// ---------------------------------------------------------------------------
__global__ void k_detect(const void* ei, int N) {
    if (threadIdx.x == 0 && blockIdx.x == 0) {
        const long long* p = (const long long*)ei;
        int ok = 1;
        for (int i = 0; i < 64; i++) {
            long long v = p[i];
            if (v < 0 || v >= (long long)N) ok = 0;
        }
        g_is64 = ok;
    }
}

// ---------------------------------------------------------------------------
// CSR build
// ---------------------------------------------------------------------------
__global__ void k_zero_deg(int N) {
    int i = blockIdx.x * blockDim.x + threadIdx.x;
    if (i < N) g_deg[i] = 0;
}
__global__ void k_deg(const void* eiv, int E, int ET) {
    int i = blockIdx.x * blockDim.x + threadIdx.x;
    if (i >= ET) return;
    int dst;
    if (i >= E) dst = i - E;
    else if (g_is64) dst = (int)((const long long*)eiv)[E + i];
    else            dst = ((const int*)eiv)[E + i];
    atomicAdd(&g_deg[dst], 1);
}
__global__ void k_scan1(int N) {
    __shared__ int sh[1024];
    int i = blockIdx.x * 1024 + threadIdx.x;
    int v = (i < N) ? g_deg[i] : 0;
    sh[threadIdx.x] = v;
    __syncthreads();
    for (int o = 1; o < 1024; o <<= 1) {
        int t = (threadIdx.x >= o) ? sh[threadIdx.x - o] : 0;
        __syncthreads();
        sh[threadIdx.x] += t;
        __syncthreads();
    }
    if (i < N) g_scan[i] = sh[threadIdx.x];
    if (threadIdx.x == 1023) g_bsum[blockIdx.x] = sh[1023];
}
__global__ void k_scan2(int nb) {
    __shared__ int sh[128];
    int v = (threadIdx.x < nb) ? g_bsum[threadIdx.x] : 0;
    sh[threadIdx.x] = v;
    __syncthreads();
    for (int o = 1; o < 128; o <<= 1) {
        int t = (threadIdx.x >= o) ? sh[threadIdx.x - o] : 0;
        __syncthreads();
        sh[threadIdx.x] += t;
        __syncthreads();
    }
    if (threadIdx.x < nb) g_bsum[threadIdx.x] = sh[threadIdx.x] - v;
}
__global__ void k_scan3(int N) {
    int i = blockIdx.x * blockDim.x + threadIdx.x;
    if (i >= N) return;
    int o = g_scan[i] - g_deg[i] + g_bsum[i >> 10];
    g_off[i] = o;
    g_cur[i] = o;
}
__global__ void k_scatter(const void* eiv, int E, int ET) {
    int i = blockIdx.x * blockDim.x + threadIdx.x;
    if (i >= ET) return;
    int src, dst;
    if (i >= E) { src = i - E; dst = i - E; }
    else if (g_is64) {
        src = (int)((const long long*)eiv)[i];
        dst = (int)((const long long*)eiv)[E + i];
    } else {
        src = ((const int*)eiv)[i];
        dst = ((const int*)eiv)[E + i];
    }
    int pos = atomicAdd(&g_cur[dst], 1);
    g_esrc[pos] = src;
}

// ---------------------------------------------------------------------------
// wda[d] = dot(W_dst[d, :128], att_dst)
// ---------------------------------------------------------------------------
__global__ void k_wvec(const float* __restrict__ W, const float* __restrict__ att,
                       float* __restrict__ out) {
    int d = blockIdx.x;
    float v = W[d * 128 + threadIdx.x] * att[threadIdx.x];
    for (int o = 16; o > 0; o >>= 1) v += __shfl_xor_sync(0xffffffffu, v, o);
    __shared__ float sh[4];
    if ((threadIdx.x & 31) == 0) sh[threadIdx.x >> 5] = v;
    __syncthreads();
    if (threadIdx.x == 0) out[d] = sh[0] + sh[1] + sh[2] + sh[3];
}

// ---------------------------------------------------------------------------
// Weight transpose + fp16 convert: Wt[n][k] = (half)W[k][n]
// ---------------------------------------------------------------------------
__global__ void k_wprep(const float* __restrict__ W, __half* __restrict__ Wt,
                        int KD, int ND) {
    int i = blockIdx.x * 256 + threadIdx.x;
    if (i >= KD * ND) return;
    int n = i % ND, k = i / ND;
    Wt[(size_t)n * KD + k] = __float2half(W[i]);
}

// ---------------------------------------------------------------------------
// fp16 GEMM, 2-stage pipeline: C = X[N,KD] @ W[KD,ND].  CTA 128 x ND.
// IT=float: A staged via LDG/cvt/STS (pipelined), fused adst = X·wda.
// IT=half:  A staged via cp.async.  B always cp.async.
// Fused asrc = C·att in epilogue.
// ---------------------------------------------------------------------------
template <int KD, int ND, bool HOUT, typename IT>
__global__ void __launch_bounds__(256, 2) k_gemm16(const IT* __restrict__ X,
                                                   const __half* __restrict__ Wt,
                                                   float* __restrict__ Cf,
                                                   __half* __restrict__ Ch,
                                                   const float* __restrict__ att,
                                                   float* __restrict__ asrc,
                                                   const float* __restrict__ wda,
                                                   float* __restrict__ adst,
                                                   int Nn) {
    constexpr int WN = ND / 32;
    constexpr int WM = 8 / WN;
    constexpr int MTw = (128 / WM) / 16;
    constexpr int SA = 128 * 64 * 2;
    constexpr int SB = ND * 64 * 2;
    constexpr int NK = KD / 64;
    constexpr bool F32IN = (sizeof(IT) == 4);

    extern __shared__ char smem[];
    char* bufA = smem;
    float* att_s = (float*)(smem + 2 * SA + 2 * SB);
    float* asum = att_s + ND;
    float* wda_s = asum + 128;
    uint32_t sbA = (uint32_t)__cvta_generic_to_shared(smem);
    uint32_t sbB = sbA + 2 * SA;

    int tid = threadIdx.x;
    int lane = tid & 31;
    int w = tid >> 5;
    int wm = w % WM;
    int wn = w / WM;
    int g = lane >> 2;
    int t = lane & 3;
    int bm = blockIdx.x * 128;

    if (att != nullptr)
        for (int i = tid; i < ND; i += 256) att_s[i] = att[i];
    if (F32IN && wda != nullptr)
        for (int i = tid; i < KD; i += 256) wda_s[i] = wda[i];
    if (tid < 128) asum[tid] = 0.f;

    float acc[MTw][4][4];
#pragma unroll
    for (int i = 0; i < MTw; i++)
#pragma unroll
        for (int j = 0; j < 4; j++)
#pragma unroll
            for (int k = 0; k < 4; k++) acc[i][j][k] = 0.f;
    float pacc[4] = {0.f, 0.f, 0.f, 0.f};
    float4 af0[4], af1[4];

    // ---- helpers as lambdas ----
    auto cpasyncB = [&](int buf, int k0) {
#pragma unroll
        for (int i = 0; i < ND / 32; i++) {
            int idx = tid + i * 256;
            int n = idx >> 3, seg = idx & 7;
            const __half* src = Wt + (size_t)n * KD + k0 + seg * 8;
            uint32_t dst = sbB + buf * SB + SWZ((uint32_t)(n * 128 + seg * 16));
            asm volatile("cp.async.cg.shared.global [%0], [%1], 16;" :: "r"(dst), "l"(src));
        }
    };
    auto cpasyncA = [&](int buf, int k0) {
#pragma unroll
        for (int i = 0; i < 4; i++) {
            int idx = tid + i * 256;
            int r = idx >> 3, seg = idx & 7;
            const __half* src = (const __half*)X + (size_t)(bm + r) * KD + k0 + seg * 8;
            uint32_t dst = sbA + buf * SA + SWZ((uint32_t)(r * 128 + seg * 16));
            asm volatile("cp.async.cg.shared.global [%0], [%1], 16;" :: "r"(dst), "l"(src));
        }
    };
    auto ldgA = [&](int k0) {
#pragma unroll
        for (int i = 0; i < 4; i++) {
            int idx = tid + i * 256;
            int r = idx >> 3, seg = idx & 7;
            af0[i] = make_float4(0.f, 0.f, 0.f, 0.f);
            af1[i] = af0[i];
            if (bm + r < Nn) {
                const float* s = (const float*)X + (size_t)(bm + r) * KD + k0 + seg * 8;
                af0[i] = *(const float4*)s;
                af1[i] = *(const float4*)(s + 4);
            }
        }
    };
    auto stsA = [&](int buf, int k0) {
#pragma unroll
        for (int i = 0; i < 4; i++) {
            int idx = tid + i * 256;
            int r = idx >> 3, seg = idx & 7;
            __half2 hv[4];
            hv[0] = __floats2half2_rn(af0[i].x, af0[i].y);
            hv[1] = __floats2half2_rn(af0[i].z, af0[i].w);
            hv[2] = __floats2half2_rn(af1[i].x, af1[i].y);
            hv[3] = __floats2half2_rn(af1[i].z, af1[i].w);
            if (wda != nullptr) {
                const float* wp = &wda_s[k0 + seg * 8];
                pacc[i] += af0[i].x * wp[0] + af0[i].y * wp[1] +
                           af0[i].z * wp[2] + af0[i].w * wp[3] +
                           af1[i].x * wp[4] + af1[i].y * wp[5] +
                           af1[i].z * wp[6] + af1[i].w * wp[7];
            }
            *(uint4*)(bufA + buf * SA + SWZ((uint32_t)(r * 128 + seg * 16))) = *(uint4*)hv;
        }
    };

    // ---- prologue: chunk 0 ----
    if (F32IN) {
        cpasyncB(0, 0);
        asm volatile("cp.async.commit_group;");
        ldgA(0);
        stsA(0, 0);
    } else {
        cpasyncA(0, 0);
        cpasyncB(0, 0);
        asm volatile("cp.async.commit_group;");
    }

    for (int ck = 0; ck < NK; ck++) {
        int buf = ck & 1;
        if (ck + 1 < NK) {
            int nb2 = (ck + 1) & 1;
            if (F32IN) {
                cpasyncB(nb2, (ck + 1) * 64);
                asm volatile("cp.async.commit_group;");
                ldgA((ck + 1) * 64);
            } else {
                cpasyncA(nb2, (ck + 1) * 64);
                cpasyncB(nb2, (ck + 1) * 64);
                asm volatile("cp.async.commit_group;");
            }
            asm volatile("cp.async.wait_group 1;");
        } else {
            asm volatile("cp.async.wait_group 0;");
        }
        __syncthreads();
        uint32_t bA = sbA + buf * SA;
        uint32_t bB = sbB + buf * SB;
#pragma unroll
        for (int ks = 0; ks < 4; ks++) {
            int kb = ks * 32 + ((lane >> 4) << 4);
            uint32_t a[MTw][4];
#pragma unroll
            for (int mt = 0; mt < MTw; mt++) {
                int row = (wm * MTw + mt) * 16 + (lane & 15);
                uint32_t off = SWZ((uint32_t)(row * 128 + kb));
                asm volatile("ldmatrix.sync.aligned.m8n8.x4.shared.b16 {%0,%1,%2,%3}, [%4];"
                             : "=r"(a[mt][0]), "=r"(a[mt][1]), "=r"(a[mt][2]), "=r"(a[mt][3])
                             : "r"(bA + off));
            }
            uint32_t b[4][2];
#pragma unroll
            for (int np = 0; np < 2; np++) {
                int nrow = wn * 32 + np * 16 + (lane & 15);
                uint32_t off = SWZ((uint32_t)(nrow * 128 + kb));
                uint32_t r0, r1, r2, r3;
                asm volatile("ldmatrix.sync.aligned.m8n8.x4.shared.b16 {%0,%1,%2,%3}, [%4];"
                             : "=r"(r0), "=r"(r1), "=r"(r2), "=r"(r3)
                             : "r"(bB + off));
                b[np * 2][0] = r0; b[np * 2 + 1][0] = r1;
                b[np * 2][1] = r2; b[np * 2 + 1][1] = r3;
            }
#pragma unroll
            for (int mt = 0; mt < MTw; mt++)
#pragma unroll
                for (int nt = 0; nt < 4; nt++) {
                    asm volatile(
                        "mma.sync.aligned.m16n8k16.row.col.f32.f16.f16.f32 "
                        "{%0,%1,%2,%3}, {%4,%5,%6,%7}, {%8,%9}, {%0,%1,%2,%3};"
                        : "+f"(acc[mt][nt][0]), "+f"(acc[mt][nt][1]),
                          "+f"(acc[mt][nt][2]), "+f"(acc[mt][nt][3])
                        : "r"(a[mt][0]), "r"(a[mt][1]), "r"(a[mt][2]), "r"(a[mt][3]),
                          "r"(b[nt][0]), "r"(b[nt][1]));
                }
        }
        if (F32IN && ck + 1 < NK) stsA((ck + 1) & 1, (ck + 1) * 64);
        __syncthreads();
    }
    // ---- adst final (fp32 path): 8-lane reduce, direct store ----
    if (F32IN && wda != nullptr) {
#pragma unroll
        for (int i = 0; i < 4; i++) {
            float p = pacc[i];
            p += __shfl_xor_sync(0xffffffffu, p, 1);
            p += __shfl_xor_sync(0xffffffffu, p, 2);
            p += __shfl_xor_sync(0xffffffffu, p, 4);
            if ((lane & 7) == 0) {
                int r = (tid >> 3) + i * 32;
                if (bm + r < Nn) adst[bm + r] = p;
            }
        }
    }
    // ---- asrc partials ----
    if (att != nullptr) {
#pragma unroll
        for (int mt = 0; mt < MTw; mt++) {
            float s0 = 0.f, s1 = 0.f;
#pragma unroll
            for (int nt = 0; nt < 4; nt++) {
                int c0 = wn * 32 + nt * 8 + t * 2;
                float a0 = att_s[c0], a1 = att_s[c0 + 1];
                s0 += acc[mt][nt][0] * a0 + acc[mt][nt][1] * a1;
                s1 += acc[mt][nt][2] * a0 + acc[mt][nt][3] * a1;
            }
            s0 += __shfl_xor_sync(0xffffffffu, s0, 1);
            s0 += __shfl_xor_sync(0xffffffffu, s0, 2);
            s1 += __shfl_xor_sync(0xffffffffu, s1, 1);
            s1 += __shfl_xor_sync(0xffffffffu, s1, 2);
            if (t == 0) {
                int rl = (wm * MTw + mt) * 16 + g;
                atomicAdd(&asum[rl], s0);
                atomicAdd(&asum[rl + 8], s1);
            }
        }
    }
    // ---- store C ----
#pragma unroll
    for (int mt = 0; mt < MTw; mt++) {
        int r0 = bm + (wm * MTw + mt) * 16 + g;
        int r1 = r0 + 8;
#pragma unroll
        for (int nt = 0; nt < 4; nt++) {
            int c0 = wn * 32 + nt * 8 + t * 2;
            if (HOUT) {
                if (r0 < Nn)
                    *(__half2*)(Ch + (size_t)r0 * ND + c0) =
                        __floats2half2_rn(acc[mt][nt][0], acc[mt][nt][1]);
                if (r1 < Nn)
                    *(__half2*)(Ch + (size_t)r1 * ND + c0) =
                        __floats2half2_rn(acc[mt][nt][2], acc[mt][nt][3]);
            } else {
                if (r0 < Nn)
                    *(float2*)(Cf + (size_t)r0 * ND + c0) =
                        make_float2(acc[mt][nt][0], acc[mt][nt][1]);
                if (r1 < Nn)
                    *(float2*)(Cf + (size_t)r1 * ND + c0) =
                        make_float2(acc[mt][nt][2], acc[mt][nt][3]);
            }
        }
    }
    if (att != nullptr) {
        __syncthreads();
        if (tid < 128 && bm + tid < Nn) asrc[bm + tid] = asum[tid];
    }
}

// ---------------------------------------------------------------------------
// Two-phase warp-per-node aggregation (fp16 in/out); optional fused
// adst_next = relu_out · wda_next.
// ---------------------------------------------------------------------------
__global__ void __launch_bounds__(256) k_agg(const __half* __restrict__ H,
                                             const float* __restrict__ asrc,
                                             const float* __restrict__ adst,
                                             const float* __restrict__ bias,
                                             __half* __restrict__ out,
                                             const float* __restrict__ wda2,
                                             float* __restrict__ adst2, int N) {
    __shared__ int   ss[8][64];
    __shared__ float pp[8][64];
    int wl = threadIdx.x >> 5;
    int lane = threadIdx.x & 31;
    int w = blockIdx.x * 8 + wl;
    if (w >= N) return;
    int st = g_off[w];
    int d = g_deg[w];
    float ad = adst[w];

    int half = lane >> 4;
    int l16 = lane & 15;
    float den = 0.f;
    float acc[8];
#pragma unroll
    for (int i = 0; i < 8; i++) acc[i] = 0.f;

    for (int c0 = 0; c0 < d; c0 += 64) {
        int nc = min(64, d - c0);
        for (int j = lane; j < nc; j += 32) {
            int s = g_esrc[st + c0 + j];
            float e = asrc[s] + ad;
            e = (e >= 0.f) ? e : 0.2f * e;
            float p = __expf(e);
            ss[wl][j] = s;
            pp[wl][j] = p;
            den += p;
        }
        __syncwarp();
#pragma unroll 4
        for (int j = half; j < nc; j += 2) {
            int s = ss[wl][j];
            float p = pp[wl][j];
            uint4 hv = *(const uint4*)(H + (size_t)s * 128 + l16 * 8);
            float2 f0 = __half22float2(*(const __half2*)&hv.x);
            float2 f1 = __half22float2(*(const __half2*)&hv.y);
            float2 f2 = __half22float2(*(const __half2*)&hv.z);
            float2 f3 = __half22float2(*(const __half2*)&hv.w);
            acc[0] = fmaf(p, f0.x, acc[0]);
            acc[1] = fmaf(p, f0.y, acc[1]);
            acc[2] = fmaf(p, f1.x, acc[2]);
            acc[3] = fmaf(p, f1.y, acc[3]);
            acc[4] = fmaf(p, f2.x, acc[4]);
            acc[5] = fmaf(p, f2.y, acc[5]);
            acc[6] = fmaf(p, f3.x, acc[6]);
            acc[7] = fmaf(p, f3.y, acc[7]);
        }
        __syncwarp();
    }
    for (int o = 16; o > 0; o >>= 1) den += __shfl_xor_sync(0xffffffffu, den, o);
#pragma unroll
    for (int i = 0; i < 8; i++) acc[i] += __shfl_xor_sync(0xffffffffu, acc[i], 16);

    if (half == 0) {
        float inv = 1.0f / den;
        float4 b0 = *(const float4*)(bias + l16 * 8);
        float4 b1 = *(const float4*)(bias + l16 * 8 + 4);
        float o0 = fmaxf(fmaf(acc[0], inv, b0.x), 0.f);
        float o1 = fmaxf(fmaf(acc[1], inv, b0.y), 0.f);
        float o2 = fmaxf(fmaf(acc[2], inv, b0.z), 0.f);
        float o3 = fmaxf(fmaf(acc[3], inv, b0.w), 0.f);
        float o4 = fmaxf(fmaf(acc[4], inv, b1.x), 0.f);
        float o5 = fmaxf(fmaf(acc[5], inv, b1.y), 0.f);
        float o6 = fmaxf(fmaf(acc[6], inv, b1.z), 0.f);
        float o7 = fmaxf(fmaf(acc[7], inv, b1.w), 0.f);
        __half2 hh[4];
        hh[0] = __floats2half2_rn(o0, o1);
        hh[1] = __floats2half2_rn(o2, o3);
        hh[2] = __floats2half2_rn(o4, o5);
        hh[3] = __floats2half2_rn(o6, o7);
        *(uint4*)(out + (size_t)w * 128 + l16 * 8) = *(uint4*)hh;
        if (wda2 != nullptr) {
            const float* wp = wda2 + l16 * 8;
            float sd = o0 * wp[0] + o1 * wp[1] + o2 * wp[2] + o3 * wp[3] +
                       o4 * wp[4] + o5 * wp[5] + o6 * wp[6] + o7 * wp[7];
            for (int o = 8; o > 0; o >>= 1) sd += __shfl_xor_sync(0x0000ffffu, sd, o);
            if (l16 == 0) adst2[w] = sd;
        }
    }
}

// ---------------------------------------------------------------------------
// BN stats (read-only) + final
// ---------------------------------------------------------------------------
__global__ void k_zero_bn() {
    if (threadIdx.x < 128) g_bn[threadIdx.x] = 0.f;
}
__global__ void __launch_bounds__(256) k_bstats(const float* __restrict__ H3,
                                                const float* __restrict__ b, int N) {
    int c = threadIdx.x & 63;
    int rg = threadIdx.x >> 6;
    float bc = b[c];
    float s = 0.f, q = 0.f;
    for (int r = blockIdx.x * 4 + rg; r < N; r += gridDim.x * 4) {
        float v = H3[(size_t)r * 64 + c] + bc;
        s += v;
        q += v * v;
    }
    __shared__ float ss[4][64], qq[4][64];
    ss[rg][c] = s;
    qq[rg][c] = q;
    __syncthreads();
    if (threadIdx.x < 64) {
        float S = ss[0][c] + ss[1][c] + ss[2][c] + ss[3][c];
        float Q = qq[0][c] + qq[1][c] + qq[2][c] + qq[3][c];
        atomicAdd(&g_bn[c], S);
        atomicAdd(&g_bn[64 + c], Q);
    }
}
__global__ void k_bnfinal(int N) {
    int c = threadIdx.x;
    float invN = 1.0f / (float)N;
    float m = g_bn[c] * invN;
    float v = g_bn[64 + c] * invN - m * m;
    g_mu[c] = m;
    g_rstd[c] = rsqrtf(v + 1e-5f);
}

// ---------------------------------------------------------------------------
// Head: +fc1_b, BN-normalize + relu + fc2 (64x40) + log_softmax. Warp per row.
// ---------------------------------------------------------------------------
__global__ void __launch_bounds__(256) k_head(const float* __restrict__ H3,
                                              const float* __restrict__ b1f,
                                              const float* __restrict__ W2,
                                              const float* __restrict__ b2,
                                              const float* __restrict__ gamma,
                                              const float* __restrict__ beta,
                                              float* __restrict__ out, int N) {
    __shared__ float Ws[64][40];
    __shared__ float cb[40], cg[64], cbt[64], cmu[64], crs[64], cfb[64];
    __shared__ float xs[8][64];
    int tid = threadIdx.x;
    for (int i = tid; i < 64 * 40; i += 256) Ws[i / 40][i % 40] = W2[i];
    if (tid < 40) cb[tid] = b2[tid];
    if (tid < 64) {
        cg[tid] = gamma[tid];
        cbt[tid] = beta[tid];
        cmu[tid] = g_mu[tid];
        crs[tid] = g_rstd[tid];
        cfb[tid] = b1f[tid];
    }
    __syncthreads();
    int w = tid >> 5, lane = tid & 31;
    int row = blockIdx.x * 8 + w;
    if (row >= N) return;
    float v0 = H3[(size_t)row * 64 + lane] + cfb[lane];
    int l2 = 32 + lane;
    float v1 = H3[(size_t)row * 64 + l2] + cfb[l2];
    v0 = fmaxf((v0 - cmu[lane]) * crs[lane] * cg[lane] + cbt[lane], 0.f);
    v1 = fmaxf((v1 - cmu[l2]) * crs[l2] * cg[l2] + cbt[l2], 0.f);
    xs[w][lane] = v0;
    xs[w][l2] = v1;
    __syncwarp();
    float o0 = cb[lane];
    float o1 = (lane < 8) ? cb[32 + lane] : 0.f;
#pragma unroll
    for (int k = 0; k < 64; k++) {
        float xv = xs[w][k];
        o0 = fmaf(xv, Ws[k][lane], o0);
        if (lane < 8) o1 = fmaf(xv, Ws[k][32 + lane], o1);
    }
    float mx = (lane < 8) ? fmaxf(o0, o1) : o0;
    for (int o = 16; o > 0; o >>= 1) mx = fmaxf(mx, __shfl_xor_sync(0xffffffffu, mx, o));
    float s = expf(o0 - mx) + ((lane < 8) ? expf(o1 - mx) : 0.f);
    for (int o = 16; o > 0; o >>= 1) s += __shfl_xor_sync(0xffffffffu, s, o);
    float lse = mx + logf(s);
    out[(size_t)row * 40 + lane] = o0 - lse;
    if (lane < 8) out[(size_t)row * 40 + 32 + lane] = o1 - lse;
}

// ---------------------------------------------------------------------------
// Launch
// ---------------------------------------------------------------------------
extern "C" void kernel_launch(void* const* d_in, const int* in_sizes, int n_in,
                              void* d_out, int out_size) {
    const float* x        = (const float*)d_in[0];
    const void*  ei       = d_in[1];
    const float* W1_src   = (const float*)d_in[2];
    const float* W1_dst   = (const float*)d_in[3];
    const float* att1_src = (const float*)d_in[4];
    const float* att1_dst = (const float*)d_in[5];
    const float* b1       = (const float*)d_in[6];
    const float* W2_src   = (const float*)d_in[7];
    const float* W2_dst   = (const float*)d_in[8];
    const float* att2_src = (const float*)d_in[9];
    const float* att2_dst = (const float*)d_in[10];
    const float* b2       = (const float*)d_in[11];
    const float* fc1_w    = (const float*)d_in[12];
    const float* fc1_b    = (const float*)d_in[13];
    const float* gamma    = (const float*)d_in[14];
    const float* beta     = (const float*)d_in[15];
    const float* fc2_w    = (const float*)d_in[16];
    const float* fc2_b    = (const float*)d_in[17];
    float* out = (float*)d_out;

    int N = in_sizes[0] / 256;
    int E = in_sizes[1] / 2;
    int ET = E + N;

    float *pA, *pB, *pH3, *pAsrc, *pAdst, *pWda;
    __half* pWt;
    cudaGetSymbolAddress((void**)&pA, g_A);
    cudaGetSymbolAddress((void**)&pB, g_B);
    cudaGetSymbolAddress((void**)&pH3, g_h3);
    cudaGetSymbolAddress((void**)&pAsrc, g_asrc);
    cudaGetSymbolAddress((void**)&pAdst, g_adst);
    cudaGetSymbolAddress((void**)&pWda, g_wda);
    cudaGetSymbolAddress((void**)&pWt, g_Wt);
    __half* pAh = (__half*)pA;
    __half* pBh = (__half*)pB;

    static bool attr_done = false;
    if (!attr_done) {
        cudaFuncSetAttribute((const void*)k_gemm16<256, 128, true, float>,
                             cudaFuncAttributeMaxDynamicSharedMemorySize, 67584);
        cudaFuncSetAttribute((const void*)k_gemm16<128, 128, true, __half>,
                             cudaFuncAttributeMaxDynamicSharedMemorySize, 67584);
        cudaFuncSetAttribute((const void*)k_gemm16<128, 64, false, __half>,
                             cudaFuncAttributeMaxDynamicSharedMemorySize, 50944);
        attr_done = true;
    }

    int nb = (N + 1023) / 1024;
    int gM = (N + 127) / 128;
    int gW = (N + 7) / 8;

    // ---- Layer-1 prep + GEMM (keep gemm1 in the profiled slot #4) ----
    k_wvec<<<256, 128>>>(W1_dst, att1_dst, pWda);                       // 1
    k_wprep<<<(256 * 128 + 255) / 256, 256>>>(W1_src, pWt, 256, 128);   // 2
    k_detect<<<1, 32>>>(ei, N);                                         // 3
    k_gemm16<256, 128, true, float><<<gM, 256, 67584>>>(                // 4
        x, pWt, nullptr, pAh, att1_src, pAsrc, pWda, pAdst, N);
    // ---- CSR build ----
    k_zero_deg<<<(N + 255) / 256, 256>>>(N);
    k_deg<<<(ET + 255) / 256, 256>>>(ei, E, ET);
    k_scan1<<<nb, 1024>>>(N);
    k_scan2<<<1, 128>>>(nb);
    k_scan3<<<(N + 255) / 256, 256>>>(N);
    k_scatter<<<(ET + 255) / 256, 256>>>(ei, E, ET);

    // wda2 must precede k_agg1 (fused adst2)
    k_wvec<<<128, 128>>>(W2_dst, att2_dst, pWda);
    k_agg<<<gW, 256>>>(pAh, pAsrc, pAdst, b1, pBh, pWda, pAdst, N);

    // ---- Layer 2 ----
    k_wprep<<<(128 * 128 + 255) / 256, 256>>>(W2_src, pWt, 128, 128);
    k_gemm16<128, 128, true, __half><<<gM, 256, 67584>>>(
        pBh, pWt, nullptr, pAh, att2_src, pAsrc, nullptr, nullptr, N);
    k_agg<<<gW, 256>>>(pAh, pAsrc, pAdst, b2, pBh, nullptr, nullptr, N);

    // ---- Head ----
    k_wprep<<<(128 * 64 + 255) / 256, 256>>>(fc1_w, pWt, 128, 64);
    k_zero_bn<<<1, 128>>>();
    k_gemm16<128, 64, false, __half><<<gM, 256, 50944>>>(
        pBh, pWt, pH3, nullptr, nullptr, nullptr, nullptr, nullptr, N);
    k_bstats<<<512, 256>>>(pH3, fc1_b, N);
    k_bnfinal<<<1, 64>>>(N);
    k_head<<<gW, 256>>>(pH3, fc1_b, fc2_w, fc2_b, gamma, beta, out, N);
}

// round 9
// speedup vs baseline: 1.5116x; 1.5116x over previous
#include <cuda_runtime.h>
#include <cuda_fp16.h>
#include <cstdint>

// ---------------------------------------------------------------------------
// GAT_37709812858998: 2-layer GAT + FC/BN/FC/log_softmax
// R9: R6 kernels verbatim (known-best) + fork/join stream overlap:
//     CSR build + layer-2/3 weight preps run concurrently with gemm1.
//     Split scratch buffers (Wt1/2/3, wda1/2) to remove WAR hazards.
// ---------------------------------------------------------------------------

#define MAXN 100096
#define MAXE 1700160

__device__ float  g_A[(size_t)MAXN * 128];   // h_src as __half (aliased)
__device__ float  g_B[(size_t)MAXN * 128];   // layer out as __half (aliased)
__device__ float  g_h3[(size_t)MAXN * 64];
__device__ float  g_asrc[MAXN];
__device__ float  g_adst[MAXN];
__device__ float  g_wda1[256];
__device__ float  g_wda2[128];
__device__ __half g_Wt1[128 * 256];
__device__ __half g_Wt2[128 * 128];
__device__ __half g_Wt3[64 * 128];
__device__ int    g_deg[MAXN];
__device__ int    g_off[MAXN];
__device__ int    g_cur[MAXN];
__device__ int    g_scan[MAXN];
__device__ int    g_bsum[256];
__device__ int    g_esrc[MAXE];
__device__ float  g_bn[128];
__device__ float  g_mu[64];
__device__ float  g_rstd[64];
__device__ int    g_is64;

#define SWZ(o) ((o) ^ (((o) >> 3) & 0x70))

// ---------------------------------------------------------------------------
__global__ void k_detect(const void* ei, int N) {
    if (threadIdx.x == 0 && blockIdx.x == 0) {
        const long long* p = (const long long*)ei;
        int ok = 1;
        for (int i = 0; i < 64; i++) {
            long long v = p[i];
            if (v < 0 || v >= (long long)N) ok = 0;
        }
        g_is64 = ok;
    }
}

// ---------------------------------------------------------------------------
// CSR build
// ---------------------------------------------------------------------------
__global__ void k_zero_deg(int N) {
    int i = blockIdx.x * blockDim.x + threadIdx.x;
    if (i < N) g_deg[i] = 0;
}
__global__ void k_deg(const void* eiv, int E, int ET) {
    int i = blockIdx.x * blockDim.x + threadIdx.x;
    if (i >= ET) return;
    int dst;
    if (i >= E) dst = i - E;
    else if (g_is64) dst = (int)((const long long*)eiv)[E + i];
    else            dst = ((const int*)eiv)[E + i];
    atomicAdd(&g_deg[dst], 1);
}
__global__ void k_scan1(int N) {
    __shared__ int sh[1024];
    int i = blockIdx.x * 1024 + threadIdx.x;
    int v = (i < N) ? g_deg[i] : 0;
    sh[threadIdx.x] = v;
    __syncthreads();
    for (int o = 1; o < 1024; o <<= 1) {
        int t = (threadIdx.x >= o) ? sh[threadIdx.x - o] : 0;
        __syncthreads();
        sh[threadIdx.x] += t;
        __syncthreads();
    }
    if (i < N) g_scan[i] = sh[threadIdx.x];
    if (threadIdx.x == 1023) g_bsum[blockIdx.x] = sh[1023];
}
__global__ void k_scan2(int nb) {
    __shared__ int sh[128];
    int v = (threadIdx.x < nb) ? g_bsum[threadIdx.x] : 0;
    sh[threadIdx.x] = v;
    __syncthreads();
    for (int o = 1; o < 128; o <<= 1) {
        int t = (threadIdx.x >= o) ? sh[threadIdx.x - o] : 0;
        __syncthreads();
        sh[threadIdx.x] += t;
        __syncthreads();
    }
    if (threadIdx.x < nb) g_bsum[threadIdx.x] = sh[threadIdx.x] - v;
}
__global__ void k_scan3(int N) {
    int i = blockIdx.x * blockDim.x + threadIdx.x;
    if (i >= N) return;
    int o = g_scan[i] - g_deg[i] + g_bsum[i >> 10];
    g_off[i] = o;
    g_cur[i] = o;
}
__global__ void k_scatter(const void* eiv, int E, int ET) {
    int i = blockIdx.x * blockDim.x + threadIdx.x;
    if (i >= ET) return;
    int src, dst;
    if (i >= E) { src = i - E; dst = i - E; }
    else if (g_is64) {
        src = (int)((const long long*)eiv)[i];
        dst = (int)((const long long*)eiv)[E + i];
    } else {
        src = ((const int*)eiv)[i];
        dst = ((const int*)eiv)[E + i];
    }
    int pos = atomicAdd(&g_cur[dst], 1);
    g_esrc[pos] = src;
}

// ---------------------------------------------------------------------------
// wda[d] = dot(W_dst[d, :128], att_dst)
// ---------------------------------------------------------------------------
__global__ void k_wvec(const float* __restrict__ W, const float* __restrict__ att,
                       float* __restrict__ out) {
    int d = blockIdx.x;
    float v = W[d * 128 + threadIdx.x] * att[threadIdx.x];
    for (int o = 16; o > 0; o >>= 1) v += __shfl_xor_sync(0xffffffffu, v, o);
    __shared__ float sh[4];
    if ((threadIdx.x & 31) == 0) sh[threadIdx.x >> 5] = v;
    __syncthreads();
    if (threadIdx.x == 0) out[d] = sh[0] + sh[1] + sh[2] + sh[3];
}

// ---------------------------------------------------------------------------
// Weight transpose + fp16 convert: Wt[n][k] = (half)W[k][n]
// ---------------------------------------------------------------------------
__global__ void k_wprep(const float* __restrict__ W, __half* __restrict__ Wt,
                        int KD, int ND) {
    int i = blockIdx.x * 256 + threadIdx.x;
    if (i >= KD * ND) return;
    int n = i % ND, k = i / ND;
    Wt[(size_t)n * KD + k] = __float2half(W[i]);
}

// ---------------------------------------------------------------------------
// fp16 GEMM via mma.sync m16n8k16 + ldmatrix (R6 version, known-best):
// C = X[N,KD] @ W[KD,ND], CTA 128 x ND, K chunk 64, single-buffered staging.
// Fused: asrc = C·att (epilogue), adst = X·wda (staging, reg-accumulated).
// ---------------------------------------------------------------------------
template <int KD, int ND, bool HOUT, typename IT>
__global__ void __launch_bounds__(256) k_gemm16(const IT* __restrict__ X,
                                                const __half* __restrict__ Wt,
                                                float* __restrict__ Cf,
                                                __half* __restrict__ Ch,
                                                const float* __restrict__ att,
                                                float* __restrict__ asrc,
                                                const float* __restrict__ wda,
                                                float* __restrict__ adst,
                                                int Nn) {
    constexpr int WN = ND / 32;          // warps along N (4 or 2)
    constexpr int WM = 8 / WN;           // warps along M (2 or 4)
    constexpr int MTw = (128 / WM) / 16; // m16-tiles per warp (4 or 2)

    __shared__ __half As[128 * 64];      // 16 KB, SW128 rows of 128B
    __shared__ __half Bs[ND * 64];       // 16/8 KB
    __shared__ float att_s[ND];
    __shared__ float wda_s[KD];
    __shared__ float asum[128];

    int tid = threadIdx.x;
    int lane = tid & 31;
    int w = tid >> 5;
    int wm = w % WM;
    int wn = w / WM;
    int g = lane >> 2;
    int t = lane & 3;
    int bm = blockIdx.x * 128;

    if (att != nullptr)
        for (int i = tid; i < ND; i += 256) att_s[i] = att[i];
    if (wda != nullptr)
        for (int i = tid; i < KD; i += 256) wda_s[i] = wda[i];
    if (tid < 128) asum[tid] = 0.f;
    __syncthreads();

    uint32_t sbA = (uint32_t)__cvta_generic_to_shared(As);
    uint32_t sbB = (uint32_t)__cvta_generic_to_shared(Bs);

    float acc[MTw][4][4];
#pragma unroll
    for (int i = 0; i < MTw; i++)
#pragma unroll
        for (int j = 0; j < 4; j++)
#pragma unroll
            for (int k = 0; k < 4; k++) acc[i][j][k] = 0.f;
    float pacc[4] = {0.f, 0.f, 0.f, 0.f};

    for (int k0 = 0; k0 < KD; k0 += 64) {
        // ---- stage A: 128 rows x 64 halfs (8 halfs = 16B per seg) ----
#pragma unroll
        for (int i = 0; i < 4; i++) {
            int idx = tid + i * 256;
            int r = idx >> 3;
            int seg = idx & 7;
            __half2 hv[4];
            if (sizeof(IT) == 4) {
                const float* src = (const float*)X + (size_t)(bm + r) * KD + k0 + seg * 8;
                float4 f0 = make_float4(0.f, 0.f, 0.f, 0.f), f1 = f0;
                if (bm + r < Nn) { f0 = *(const float4*)src; f1 = *(const float4*)(src + 4); }
                hv[0] = __floats2half2_rn(f0.x, f0.y);
                hv[1] = __floats2half2_rn(f0.z, f0.w);
                hv[2] = __floats2half2_rn(f1.x, f1.y);
                hv[3] = __floats2half2_rn(f1.z, f1.w);
                if (wda != nullptr) {
                    const float* wp = &wda_s[k0 + seg * 8];
                    pacc[i] += f0.x * wp[0] + f0.y * wp[1] + f0.z * wp[2] + f0.w * wp[3] +
                               f1.x * wp[4] + f1.y * wp[5] + f1.z * wp[6] + f1.w * wp[7];
                }
            } else {
                uint4 u = make_uint4(0, 0, 0, 0);
                if (bm + r < Nn)
                    u = *(const uint4*)((const __half*)X + (size_t)(bm + r) * KD + k0 + seg * 8);
                hv[0] = *(__half2*)&u.x; hv[1] = *(__half2*)&u.y;
                hv[2] = *(__half2*)&u.z; hv[3] = *(__half2*)&u.w;
                if (wda != nullptr) {
                    const float* wp = &wda_s[k0 + seg * 8];
                    float2 a0 = __half22float2(hv[0]), a1 = __half22float2(hv[1]);
                    float2 a2 = __half22float2(hv[2]), a3 = __half22float2(hv[3]);
                    pacc[i] += a0.x * wp[0] + a0.y * wp[1] + a1.x * wp[2] + a1.y * wp[3] +
                               a2.x * wp[4] + a2.y * wp[5] + a3.x * wp[6] + a3.y * wp[7];
                }
            }
            uint32_t off = (uint32_t)(r * 128 + seg * 16);
            *(uint4*)((char*)As + SWZ(off)) = *(uint4*)hv;
        }
        // ---- stage B: ND rows x 64 halfs from Wt ----
#pragma unroll
        for (int i = 0; i < ND / 32; i++) {
            int idx = tid + i * 256;
            int n = idx >> 3;
            int seg = idx & 7;
            uint4 u = *(const uint4*)(Wt + (size_t)n * KD + k0 + seg * 8);
            uint32_t off = (uint32_t)(n * 128 + seg * 16);
            *(uint4*)((char*)Bs + SWZ(off)) = u;
        }
        __syncthreads();
        // ---- compute: 4 k16 steps ----
#pragma unroll
        for (int ks = 0; ks < 4; ks++) {
            int kb = ks * 32 + ((lane >> 4) << 4);
            uint32_t a[MTw][4];
#pragma unroll
            for (int mt = 0; mt < MTw; mt++) {
                int row = (wm * MTw + mt) * 16 + (lane & 15);
                uint32_t off = SWZ((uint32_t)(row * 128 + kb));
                asm volatile("ldmatrix.sync.aligned.m8n8.x4.shared.b16 {%0,%1,%2,%3}, [%4];"
                             : "=r"(a[mt][0]), "=r"(a[mt][1]), "=r"(a[mt][2]), "=r"(a[mt][3])
                             : "r"(sbA + off));
            }
            uint32_t b[4][2];
#pragma unroll
            for (int np = 0; np < 2; np++) {
                int nrow = wn * 32 + np * 16 + (lane & 15);
                uint32_t off = SWZ((uint32_t)(nrow * 128 + kb));
                uint32_t r0, r1, r2, r3;
                asm volatile("ldmatrix.sync.aligned.m8n8.x4.shared.b16 {%0,%1,%2,%3}, [%4];"
                             : "=r"(r0), "=r"(r1), "=r"(r2), "=r"(r3)
                             : "r"(sbB + off));
                b[np * 2][0] = r0; b[np * 2 + 1][0] = r1;
                b[np * 2][1] = r2; b[np * 2 + 1][1] = r3;
            }
#pragma unroll
            for (int mt = 0; mt < MTw; mt++)
#pragma unroll
                for (int nt = 0; nt < 4; nt++) {
                    asm volatile(
                        "mma.sync.aligned.m16n8k16.row.col.f32.f16.f16.f32 "
                        "{%0,%1,%2,%3}, {%4,%5,%6,%7}, {%8,%9}, {%0,%1,%2,%3};"
                        : "+f"(acc[mt][nt][0]), "+f"(acc[mt][nt][1]),
                          "+f"(acc[mt][nt][2]), "+f"(acc[mt][nt][3])
                        : "r"(a[mt][0]), "r"(a[mt][1]), "r"(a[mt][2]), "r"(a[mt][3]),
                          "r"(b[nt][0]), "r"(b[nt][1]));
                }
        }
        __syncthreads();
    }
    // ---- adst final: 8-lane reduce, direct store ----
    if (wda != nullptr) {
#pragma unroll
        for (int i = 0; i < 4; i++) {
            float p = pacc[i];
            p += __shfl_xor_sync(0xffffffffu, p, 1);
            p += __shfl_xor_sync(0xffffffffu, p, 2);
            p += __shfl_xor_sync(0xffffffffu, p, 4);
            if ((lane & 7) == 0) {
                int r = (tid >> 3) + i * 32;
                if (bm + r < Nn) adst[bm + r] = p;
            }
        }
    }
    // ---- asrc partials ----
    if (att != nullptr) {
#pragma unroll
        for (int mt = 0; mt < MTw; mt++) {
            float s0 = 0.f, s1 = 0.f;
#pragma unroll
            for (int nt = 0; nt < 4; nt++) {
                int c0 = wn * 32 + nt * 8 + t * 2;
                float a0 = att_s[c0], a1 = att_s[c0 + 1];
                s0 += acc[mt][nt][0] * a0 + acc[mt][nt][1] * a1;
                s1 += acc[mt][nt][2] * a0 + acc[mt][nt][3] * a1;
            }
            s0 += __shfl_xor_sync(0xffffffffu, s0, 1);
            s0 += __shfl_xor_sync(0xffffffffu, s0, 2);
            s1 += __shfl_xor_sync(0xffffffffu, s1, 1);
            s1 += __shfl_xor_sync(0xffffffffu, s1, 2);
            if (t == 0) {
                int rl = (wm * MTw + mt) * 16 + g;
                atomicAdd(&asum[rl], s0);
                atomicAdd(&asum[rl + 8], s1);
            }
        }
    }
    // ---- store C ----
#pragma unroll
    for (int mt = 0; mt < MTw; mt++) {
        int r0 = bm + (wm * MTw + mt) * 16 + g;
        int r1 = r0 + 8;
#pragma unroll
        for (int nt = 0; nt < 4; nt++) {
            int c0 = wn * 32 + nt * 8 + t * 2;
            if (HOUT) {
                if (r0 < Nn)
                    *(__half2*)(Ch + (size_t)r0 * ND + c0) =
                        __floats2half2_rn(acc[mt][nt][0], acc[mt][nt][1]);
                if (r1 < Nn)
                    *(__half2*)(Ch + (size_t)r1 * ND + c0) =
                        __floats2half2_rn(acc[mt][nt][2], acc[mt][nt][3]);
            } else {
                if (r0 < Nn)
                    *(float2*)(Cf + (size_t)r0 * ND + c0) =
                        make_float2(acc[mt][nt][0], acc[mt][nt][1]);
                if (r1 < Nn)
                    *(float2*)(Cf + (size_t)r1 * ND + c0) =
                        make_float2(acc[mt][nt][2], acc[mt][nt][3]);
            }
        }
    }
    if (att != nullptr) {
        __syncthreads();
        if (tid < 128 && bm + tid < Nn) asrc[bm + tid] = asum[tid];
    }
}

// ---------------------------------------------------------------------------
// Two-phase warp-per-node aggregation (fp16 in/out)
// ---------------------------------------------------------------------------
__global__ void __launch_bounds__(256) k_agg(const __half* __restrict__ H,
                                             const float* __restrict__ asrc,
                                             const float* __restrict__ adst,
                                             const float* __restrict__ bias,
                                             __half* __restrict__ out, int N) {
    __shared__ int   ss[8][64];
    __shared__ float pp[8][64];
    int wl = threadIdx.x >> 5;
    int lane = threadIdx.x & 31;
    int w = blockIdx.x * 8 + wl;
    if (w >= N) return;
    int st = g_off[w];
    int d = g_deg[w];
    float ad = adst[w];

    int half = lane >> 4;
    int l16 = lane & 15;
    float den = 0.f;
    float acc[8];
#pragma unroll
    for (int i = 0; i < 8; i++) acc[i] = 0.f;

    for (int c0 = 0; c0 < d; c0 += 64) {
        int nc = min(64, d - c0);
        for (int j = lane; j < nc; j += 32) {
            int s = g_esrc[st + c0 + j];
            float e = asrc[s] + ad;
            e = (e >= 0.f) ? e : 0.2f * e;
            float p = __expf(e);
            ss[wl][j] = s;
            pp[wl][j] = p;
            den += p;
        }
        __syncwarp();
#pragma unroll 4
        for (int j = half; j < nc; j += 2) {
            int s = ss[wl][j];
            float p = pp[wl][j];
            uint4 hv = *(const uint4*)(H + (size_t)s * 128 + l16 * 8);
            float2 f0 = __half22float2(*(const __half2*)&hv.x);
            float2 f1 = __half22float2(*(const __half2*)&hv.y);
            float2 f2 = __half22float2(*(const __half2*)&hv.z);
            float2 f3 = __half22float2(*(const __half2*)&hv.w);
            acc[0] = fmaf(p, f0.x, acc[0]);
            acc[1] = fmaf(p, f0.y, acc[1]);
            acc[2] = fmaf(p, f1.x, acc[2]);
            acc[3] = fmaf(p, f1.y, acc[3]);
            acc[4] = fmaf(p, f2.x, acc[4]);
            acc[5] = fmaf(p, f2.y, acc[5]);
            acc[6] = fmaf(p, f3.x, acc[6]);
            acc[7] = fmaf(p, f3.y, acc[7]);
        }
        __syncwarp();
    }
    for (int o = 16; o > 0; o >>= 1) den += __shfl_xor_sync(0xffffffffu, den, o);
#pragma unroll
    for (int i = 0; i < 8; i++) acc[i] += __shfl_xor_sync(0xffffffffu, acc[i], 16);

    if (half == 0) {
        float inv = 1.0f / den;
        float4 b0 = *(const float4*)(bias + l16 * 8);
        float4 b1 = *(const float4*)(bias + l16 * 8 + 4);
        __half2 hh[4];
        hh[0] = __floats2half2_rn(fmaxf(fmaf(acc[0], inv, b0.x), 0.f),
                                  fmaxf(fmaf(acc[1], inv, b0.y), 0.f));
        hh[1] = __floats2half2_rn(fmaxf(fmaf(acc[2], inv, b0.z), 0.f),
                                  fmaxf(fmaf(acc[3], inv, b0.w), 0.f));
        hh[2] = __floats2half2_rn(fmaxf(fmaf(acc[4], inv, b1.x), 0.f),
                                  fmaxf(fmaf(acc[5], inv, b1.y), 0.f));
        hh[3] = __floats2half2_rn(fmaxf(fmaf(acc[6], inv, b1.z), 0.f),
                                  fmaxf(fmaf(acc[7], inv, b1.w), 0.f));
        *(uint4*)(out + (size_t)w * 128 + l16 * 8) = *(uint4*)hh;
    }
}

// ---------------------------------------------------------------------------
// BN stats (read-only) + final
// ---------------------------------------------------------------------------
__global__ void k_zero_bn() {
    if (threadIdx.x < 128) g_bn[threadIdx.x] = 0.f;
}
__global__ void __launch_bounds__(256) k_bstats(const float* __restrict__ H3,
                                                const float* __restrict__ b, int N) {
    int c = threadIdx.x & 63;
    int rg = threadIdx.x >> 6;
    float bc = b[c];
    float s = 0.f, q = 0.f;
    for (int r = blockIdx.x * 4 + rg; r < N; r += gridDim.x * 4) {
        float v = H3[(size_t)r * 64 + c] + bc;
        s += v;
        q += v * v;
    }
    __shared__ float ss[4][64], qq[4][64];
    ss[rg][c] = s;
    qq[rg][c] = q;
    __syncthreads();
    if (threadIdx.x < 64) {
        float S = ss[0][c] + ss[1][c] + ss[2][c] + ss[3][c];
        float Q = qq[0][c] + qq[1][c] + qq[2][c] + qq[3][c];
        atomicAdd(&g_bn[c], S);
        atomicAdd(&g_bn[64 + c], Q);
    }
}
__global__ void k_bnfinal(int N) {
    int c = threadIdx.x;
    float invN = 1.0f / (float)N;
    float m = g_bn[c] * invN;
    float v = g_bn[64 + c] * invN - m * m;
    g_mu[c] = m;
    g_rstd[c] = rsqrtf(v + 1e-5f);
}

// ---------------------------------------------------------------------------
// Head: +fc1_b, BN-normalize + relu + fc2 (64x40) + log_softmax. Warp per row.
// ---------------------------------------------------------------------------
__global__ void __launch_bounds__(256) k_head(const float* __restrict__ H3,
                                              const float* __restrict__ b1f,
                                              const float* __restrict__ W2,
                                              const float* __restrict__ b2,
                                              const float* __restrict__ gamma,
                                              const float* __restrict__ beta,
                                              float* __restrict__ out, int N) {
    __shared__ float Ws[64][40];
    __shared__ float cb[40], cg[64], cbt[64], cmu[64], crs[64], cfb[64];
    __shared__ float xs[8][64];
    int tid = threadIdx.x;
    for (int i = tid; i < 64 * 40; i += 256) Ws[i / 40][i % 40] = W2[i];
    if (tid < 40) cb[tid] = b2[tid];
    if (tid < 64) {
        cg[tid] = gamma[tid];
        cbt[tid] = beta[tid];
        cmu[tid] = g_mu[tid];
        crs[tid] = g_rstd[tid];
        cfb[tid] = b1f[tid];
    }
    __syncthreads();
    int w = tid >> 5, lane = tid & 31;
    int row = blockIdx.x * 8 + w;
    if (row >= N) return;
    float v0 = H3[(size_t)row * 64 + lane] + cfb[lane];
    int l2 = 32 + lane;
    float v1 = H3[(size_t)row * 64 + l2] + cfb[l2];
    v0 = fmaxf((v0 - cmu[lane]) * crs[lane] * cg[lane] + cbt[lane], 0.f);
    v1 = fmaxf((v1 - cmu[l2]) * crs[l2] * cg[l2] + cbt[l2], 0.f);
    xs[w][lane] = v0;
    xs[w][l2] = v1;
    __syncwarp();
    float o0 = cb[lane];
    float o1 = (lane < 8) ? cb[32 + lane] : 0.f;
#pragma unroll
    for (int k = 0; k < 64; k++) {
        float xv = xs[w][k];
        o0 = fmaf(xv, Ws[k][lane], o0);
        if (lane < 8) o1 = fmaf(xv, Ws[k][32 + lane], o1);
    }
    float mx = (lane < 8) ? fmaxf(o0, o1) : o0;
    for (int o = 16; o > 0; o >>= 1) mx = fmaxf(mx, __shfl_xor_sync(0xffffffffu, mx, o));
    float s = expf(o0 - mx) + ((lane < 8) ? expf(o1 - mx) : 0.f);
    for (int o = 16; o > 0; o >>= 1) s += __shfl_xor_sync(0xffffffffu, s, o);
    float lse = mx + logf(s);
    out[(size_t)row * 40 + lane] = o0 - lse;
    if (lane < 8) out[(size_t)row * 40 + 32 + lane] = o1 - lse;
}

// ---------------------------------------------------------------------------
// Launch: fork/join stream overlap (graph-capture-legal).
// ---------------------------------------------------------------------------
extern "C" void kernel_launch(void* const* d_in, const int* in_sizes, int n_in,
                              void* d_out, int out_size) {
    const float* x        = (const float*)d_in[0];
    const void*  ei       = d_in[1];
    const float* W1_src   = (const float*)d_in[2];
    const float* W1_dst   = (const float*)d_in[3];
    const float* att1_src = (const float*)d_in[4];
    const float* att1_dst = (const float*)d_in[5];
    const float* b1       = (const float*)d_in[6];
    const float* W2_src   = (const float*)d_in[7];
    const float* W2_dst   = (const float*)d_in[8];
    const float* att2_src = (const float*)d_in[9];
    const float* att2_dst = (const float*)d_in[10];
    const float* b2       = (const float*)d_in[11];
    const float* fc1_w    = (const float*)d_in[12];
    const float* fc1_b    = (const float*)d_in[13];
    const float* gamma    = (const float*)d_in[14];
    const float* beta     = (const float*)d_in[15];
    const float* fc2_w    = (const float*)d_in[16];
    const float* fc2_b    = (const float*)d_in[17];
    float* out = (float*)d_out;

    int N = in_sizes[0] / 256;
    int E = in_sizes[1] / 2;
    int ET = E + N;

    float *pA, *pB, *pH3, *pAsrc, *pAdst, *pWda1, *pWda2;
    __half *pWt1, *pWt2, *pWt3;
    cudaGetSymbolAddress((void**)&pA, g_A);
    cudaGetSymbolAddress((void**)&pB, g_B);
    cudaGetSymbolAddress((void**)&pH3, g_h3);
    cudaGetSymbolAddress((void**)&pAsrc, g_asrc);
    cudaGetSymbolAddress((void**)&pAdst, g_adst);
    cudaGetSymbolAddress((void**)&pWda1, g_wda1);
    cudaGetSymbolAddress((void**)&pWda2, g_wda2);
    cudaGetSymbolAddress((void**)&pWt1, g_Wt1);
    cudaGetSymbolAddress((void**)&pWt2, g_Wt2);
    cudaGetSymbolAddress((void**)&pWt3, g_Wt3);
    __half* pAh = (__half*)pA;
    __half* pBh = (__half*)pB;

    static cudaStream_t s2 = nullptr;
    static cudaEvent_t eF = nullptr, eCSR = nullptr, eW = nullptr;
    if (s2 == nullptr) {
        cudaStreamCreateWithFlags(&s2, cudaStreamNonBlocking);
        cudaEventCreateWithFlags(&eF, cudaEventDisableTiming);
        cudaEventCreateWithFlags(&eCSR, cudaEventDisableTiming);
        cudaEventCreateWithFlags(&eW, cudaEventDisableTiming);
    }

    int nb = (N + 1023) / 1024;
    int gM = (N + 127) / 128;
    int gW = (N + 7) / 8;

    // ---- fork: side stream does CSR build + layer-2/3 preps ----
    cudaEventRecord(eF, 0);
    cudaStreamWaitEvent(s2, eF, 0);

    k_detect<<<1, 32, 0, s2>>>(ei, N);
    k_zero_deg<<<(N + 255) / 256, 256, 0, s2>>>(N);
    k_deg<<<(ET + 255) / 256, 256, 0, s2>>>(ei, E, ET);
    k_scan1<<<nb, 1024, 0, s2>>>(N);
    k_scan2<<<1, 128, 0, s2>>>(nb);
    k_scan3<<<(N + 255) / 256, 256, 0, s2>>>(N);
    k_scatter<<<(ET + 255) / 256, 256, 0, s2>>>(ei, E, ET);
    cudaEventRecord(eCSR, s2);
    k_wvec<<<128, 128, 0, s2>>>(W2_dst, att2_dst, pWda2);
    k_wprep<<<(128 * 128 + 255) / 256, 256, 0, s2>>>(W2_src, pWt2, 128, 128);
    k_wprep<<<(128 * 64 + 255) / 256, 256, 0, s2>>>(fc1_w, pWt3, 128, 64);
    k_zero_bn<<<1, 128, 0, s2>>>();
    cudaEventRecord(eW, s2);

    // ---- main: layer-1 prep + GEMM runs concurrently with the fork ----
    k_wvec<<<256, 128>>>(W1_dst, att1_dst, pWda1);
    k_wprep<<<(256 * 128 + 255) / 256, 256>>>(W1_src, pWt1, 256, 128);
    k_gemm16<256, 128, true, float><<<gM, 256>>>(
        x, pWt1, nullptr, pAh, att1_src, pAsrc, pWda1, pAdst, N);

    // ---- join CSR, then aggregate layer 1 ----
    cudaStreamWaitEvent(0, eCSR, 0);
    k_agg<<<gW, 256>>>(pAh, pAsrc, pAdst, b1, pBh, N);

    // ---- join preps, layer 2 ----
    cudaStreamWaitEvent(0, eW, 0);
    k_gemm16<128, 128, true, __half><<<gM, 256>>>(
        pBh, pWt2, nullptr, pAh, att2_src, pAsrc, pWda2, pAdst, N);
    k_agg<<<gW, 256>>>(pAh, pAsrc, pAdst, b2, pBh, N);

    // ---- head ----
    k_gemm16<128, 64, false, __half><<<gM, 256>>>(
        pBh, pWt3, pH3, nullptr, nullptr, nullptr, nullptr, nullptr, N);
    k_bstats<<<512, 256>>>(pH3, fc1_b, N);
    k_bnfinal<<<1, 64>>>(N);
    k_head<<<gW, 256>>>(pH3, fc1_b, fc2_w, fc2_b, gamma, beta, out, N);
}